// round 12
// baseline (speedup 1.0000x reference)
#include <cuda_runtime.h>

// Fused Swin window attention, fp32 + packed f32x2 FMA. One CTA per 8x8 window.
// B=4, H=W=256, C=192, WS=8, NH=6, HD=32.
// R12: 512 threads/CTA (occ 25%, 4 warps/SMSP for latency hiding), 4m x 6n
// weight-GEMM thread tiles, uniform 192-col chunks, KT=16 double-buffered
// one-barrier pipeline, conflict-aware transpose, rpb overlay, Ps-aliased buf.
//
// smem (floats):
//   Xs [192][68]  X^T (k-major, padded); reused as attn-out^T for proj
//   Qs [6][32][64], Ks [6][32][64]  d-major
//   Vs [6][64][32] token-major
//   Ps [64][68]   softmax probs (attention) / weight buf1 (GEMMs, 16x196)
//   Bt [16][196]  weight buf0 (GEMMs) / rpb table (attention)

#define XST 68
#define PST 68
#define BST 196
#define KT  16

#define SM_X 0
#define SM_Q 13056
#define SM_K 25344
#define SM_V 37632
#define SM_P 49920
#define SM_B 54272
#define SM_FLOATS 57472
#define SMEM_BYTES (SM_FLOATS * 4)

#define NT 512

typedef unsigned long long u64;

__device__ __forceinline__ u64 bc2(float v) {
    u64 r;
    asm("mov.b64 %0, {%1, %1};" : "=l"(r) : "r"(__float_as_uint(v)));
    return r;
}
__device__ __forceinline__ void fma2(u64& d, u64 a, u64 b) {
    asm("fma.rn.f32x2 %0, %1, %2, %0;" : "+l"(d) : "l"(a), "l"(b));
}
__device__ __forceinline__ u64 mul2(u64 a, u64 b) {
    u64 r;
    asm("mul.rn.f32x2 %0, %1, %2;" : "=l"(r) : "l"(a), "l"(b));
    return r;
}
__device__ __forceinline__ float2 unpk(u64 a) {
    unsigned lo, hi;
    asm("mov.b64 {%0, %1}, %2;" : "=r"(lo), "=r"(hi) : "l"(a));
    return make_float2(__uint_as_float(lo), __uint_as_float(hi));
}

__global__ __launch_bounds__(NT, 1)
void win_attn_kernel(const float* __restrict__ x,
                     const float* __restrict__ qkv_w,
                     const float* __restrict__ proj_w,
                     const float* __restrict__ proj_b,
                     const float* __restrict__ rpb,
                     float* __restrict__ out)
{
    extern __shared__ float sm[];
    float* Xs = sm + SM_X;
    float* Qs = sm + SM_Q;
    float* Ks = sm + SM_K;
    float* Vs = sm + SM_V;
    float* Ps = sm + SM_P;
    float* Rs = sm + SM_B;       // rpb table, attention phase only
    float* wb[2];
    wb[0] = sm + SM_B;           // weight buf0 (GEMM phases)
    wb[1] = sm + SM_P;           // weight buf1 aliases Ps

    const int tid  = threadIdx.x;
    const int lane = tid & 31;
    const int w    = tid >> 5;           // 0..15
    // weight-GEMM thread tile: rows m0..m0+3, cols colT..colT+5
    const int mg   = lane >> 2;          // 0..7
    const int ls   = lane & 3;           // 0..3
    const int rg   = (w & 1) * 8 + mg;   // 0..15
    const int m0   = rg * 4;
    const int colT = ((w >> 1) * 4 + ls) * 6;   // 0..186
    // attention mapping: rows i2*2..+1, cols j*4..+3 (S) / j*2..+1 (PV)
    const int i2 = tid >> 4;             // 0..31
    const int j  = tid & 15;

    const int blk = blockIdx.x;
    const int b  = blk >> 10;
    const int wy = (blk >> 5) & 31;
    const int wx = blk & 31;
    const int base = ((b * 256 + wy * 8) * 256 + wx * 8) * 192;

    // ---- load X window transposed into Xs[k][m] (conflict-aware mapping) ----
    // warp w covers token row (w&7); warps 0-7 take k-chunks 0..5, 8-15 take 6..11.
    {
        const int dm = (tid >> 2) & 7;
        const int dc = tid & 3;
        const int m  = (w & 7) * 8 + dm;
        const int ph0 = (w >> 3) * 6;
        const float* src = x + base + ((w & 7) * 256 + dm) * 192 + dc * 4 + ph0 * 16;
        float* dstb = Xs + (dc * 4 + ph0 * 16) * XST + m;
        #pragma unroll
        for (int p = 0; p < 6; p++) {
            float4 v = *(const float4*)(src + p * 16);
            float* dst = dstb + p * 16 * XST;
            dst[0]       = v.x;
            dst[XST]     = v.y;
            dst[2 * XST] = v.z;
            dst[3 * XST] = v.w;
        }
    }

    const u64 sc2 = bc2(0.17677669529663687f);  // 32^-0.5 packed

    // staging coords: tile = 16k x 192n = 768 float4. All 512 threads load one
    // (col wc0, k-rows wk0..+3); threads 0..255 load a second at col wc0+128.
    const int wc0 = tid >> 2;            // 0..127
    const int wk0 = (tid & 3) * 4;       // 0,4,8,12
    const bool two = (tid < 256);

    float4 wr0, wr1;
    // prologue: QKV chunk 0 (Q), tile 0
    wr0 = *(const float4*)(qkv_w + wc0 * 192 + wk0);
    if (two) wr1 = *(const float4*)(qkv_w + (wc0 + 128) * 192 + wk0);
    {
        float* dst = wb[0] + wk0 * BST + wc0;
        dst[0] = wr0.x; dst[BST] = wr0.y; dst[2 * BST] = wr0.z; dst[3 * BST] = wr0.w;
        if (two) {
            float* d2 = wb[0] + wk0 * BST + wc0 + 128;
            d2[0] = wr1.x; d2[BST] = wr1.y; d2[2 * BST] = wr1.z; d2[3 * BST] = wr1.w;
        }
    }
    __syncthreads();   // tile 0 staged; also orders Xs stores

    // ---- GEMM1: QKV = X @ qkv_w^T; 3 chunks (Q,K,V) x 12 K-tiles ----
    u64 acc[2][6] = {};
    for (int t = 0; t < 36; t++) {
        const int q = t % 12;
        if (t + 1 < 36) {
            const int nn = ((t + 1) / 12) * 192;
            const int nk = ((t + 1) % 12) * KT;
            wr0 = *(const float4*)(qkv_w + (nn + wc0) * 192 + nk + wk0);
            if (two) wr1 = *(const float4*)(qkv_w + (nn + wc0 + 128) * 192 + nk + wk0);
        }
        const float* bt = wb[t & 1];
        const float* xk = Xs + (q * KT) * XST;
        #pragma unroll 4
        for (int k = 0; k < KT; k++) {
            ulonglong2 aA = *(const ulonglong2*)(xk + k * XST + m0);
            const float* br = bt + k * BST + colT;
            float2 b01 = *(const float2*)br;
            float2 b23 = *(const float2*)(br + 2);
            float2 b45 = *(const float2*)(br + 4);
            u64 B0 = bc2(b01.x), B1 = bc2(b01.y), B2 = bc2(b23.x);
            u64 B3 = bc2(b23.y), B4 = bc2(b45.x), B5 = bc2(b45.y);
            fma2(acc[0][0], aA.x, B0); fma2(acc[1][0], aA.y, B0);
            fma2(acc[0][1], aA.x, B1); fma2(acc[1][1], aA.y, B1);
            fma2(acc[0][2], aA.x, B2); fma2(acc[1][2], aA.y, B2);
            fma2(acc[0][3], aA.x, B3); fma2(acc[1][3], aA.y, B3);
            fma2(acc[0][4], aA.x, B4); fma2(acc[1][4], aA.y, B4);
            fma2(acc[0][5], aA.x, B5); fma2(acc[1][5], aA.y, B5);
        }
        if (t + 1 < 36) {
            float* bn = wb[(t + 1) & 1];
            float* dst = bn + wk0 * BST + wc0;
            dst[0] = wr0.x; dst[BST] = wr0.y; dst[2 * BST] = wr0.z; dst[3 * BST] = wr0.w;
            if (two) {
                float* d2 = bn + wk0 * BST + wc0 + 128;
                d2[0] = wr1.x; d2[BST] = wr1.y; d2[2 * BST] = wr1.z; d2[3 * BST] = wr1.w;
            }
        }
        if (q == 11) {
            const int ch = t / 12;       // 0=Q 1=K 2=V
            if (ch == 0) {
                #pragma unroll
                for (int c = 0; c < 6; c++) {
                    const int col = colT + c;
                    float* qp = Qs + (col >> 5) * 2048 + (col & 31) * 64 + m0;
                    ulonglong2 cv;
                    cv.x = mul2(acc[0][c], sc2);
                    cv.y = mul2(acc[1][c], sc2);
                    *(ulonglong2*)qp = cv;
                }
            } else if (ch == 1) {
                #pragma unroll
                for (int c = 0; c < 6; c++) {
                    const int col = colT + c;
                    float* kp = Ks + (col >> 5) * 2048 + (col & 31) * 64 + m0;
                    ulonglong2 cv;
                    cv.x = acc[0][c];
                    cv.y = acc[1][c];
                    *(ulonglong2*)kp = cv;
                }
            } else {
                #pragma unroll
                for (int c = 0; c < 6; c++) {
                    const int col = colT + c;
                    float* vp = Vs + (col >> 5) * 2048 + (col & 31);
                    #pragma unroll
                    for (int mp = 0; mp < 2; mp++) {
                        float2 f = unpk(acc[mp][c]);
                        vp[(m0 + 2 * mp) * 32]     = f.x;
                        vp[(m0 + 2 * mp + 1) * 32] = f.y;
                    }
                }
            }
            #pragma unroll
            for (int mp = 0; mp < 2; mp++)
                #pragma unroll
                for (int c = 0; c < 6; c++) acc[mp][c] = 0ull;
        }
        __syncthreads();
    }

    // ---- stage rpb into Rs (overlays wb0; all wb0 reads done) + proj prefetch ----
    for (int t = tid; t < 1350; t += NT) Rs[t] = rpb[t];
    wr0 = *(const float4*)(proj_w + wc0 * 192 + wk0);
    if (two) wr1 = *(const float4*)(proj_w + (wc0 + 128) * 192 + wk0);
    __syncthreads();   // Rs ready

    // ---- rpb offsets for this thread's S tile (2 rows x 4 cols) ----
    int ridx[2][4];
    #pragma unroll
    for (int di = 0; di < 2; di++) {
        int m = i2 * 2 + di, qr = m >> 3, qc = m & 7;
        #pragma unroll
        for (int dj = 0; dj < 4; dj++) {
            int n = j * 4 + dj, kr = n >> 3, kc = n & 7;
            ridx[di][dj] = ((qr - kr + 7) * 15 + (qc - kc + 7)) * 6;
        }
    }

    // ---- attention per head ----
    for (int h = 0; h < 6; h++) {
        const float* qh = Qs + h * 2048;
        const float* kh = Ks + h * 2048;
        u64 s2[2][2] = {};
        #pragma unroll 4
        for (int d = 0; d < 32; d++) {
            float2 a      = *(const float2*)(qh + d * 64 + i2 * 2);
            ulonglong2 b2 = *(const ulonglong2*)(kh + d * 64 + j * 4);
            u64 a0 = bc2(a.x), a1 = bc2(a.y);
            fma2(s2[0][0], a0, b2.x); fma2(s2[0][1], a0, b2.y);
            fma2(s2[1][0], a1, b2.x); fma2(s2[1][1], a1, b2.y);
        }
        float p[2][4];
        #pragma unroll
        for (int di = 0; di < 2; di++) {
            float2 s01 = unpk(s2[di][0]), s23 = unpk(s2[di][1]);
            float sv0 = s01.x + Rs[ridx[di][0] + h];
            float sv1 = s01.y + Rs[ridx[di][1] + h];
            float sv2 = s23.x + Rs[ridx[di][2] + h];
            float sv3 = s23.y + Rs[ridx[di][3] + h];
            float mx = fmaxf(fmaxf(sv0, sv1), fmaxf(sv2, sv3));
            mx = fmaxf(mx, __shfl_xor_sync(0xffffffffu, mx, 8));
            mx = fmaxf(mx, __shfl_xor_sync(0xffffffffu, mx, 4));
            mx = fmaxf(mx, __shfl_xor_sync(0xffffffffu, mx, 2));
            mx = fmaxf(mx, __shfl_xor_sync(0xffffffffu, mx, 1));
            float e0 = __expf(sv0 - mx), e1 = __expf(sv1 - mx);
            float e2 = __expf(sv2 - mx), e3 = __expf(sv3 - mx);
            float sum = (e0 + e1) + (e2 + e3);
            sum += __shfl_xor_sync(0xffffffffu, sum, 8);
            sum += __shfl_xor_sync(0xffffffffu, sum, 4);
            sum += __shfl_xor_sync(0xffffffffu, sum, 2);
            sum += __shfl_xor_sync(0xffffffffu, sum, 1);
            float inv = __frcp_rn(sum);
            p[di][0] = e0 * inv; p[di][1] = e1 * inv;
            p[di][2] = e2 * inv; p[di][3] = e3 * inv;
        }
        __syncthreads();   // prior Ps readers done
        #pragma unroll
        for (int dj = 0; dj < 4; dj++)
            *(float2*)(Ps + (j * 4 + dj) * PST + i2 * 2) =
                make_float2(p[0][dj], p[1][dj]);
        __syncthreads();   // Ps ready

        // PV: rows i2*2..+1 (one packed pair), cols j*2..+1
        const float* vh = Vs + h * 2048;
        u64 o2[2] = {};
        #pragma unroll 4
        for (int kk = 0; kk < 64; kk++) {
            u64 a2 = *(const u64*)(Ps + kk * PST + i2 * 2);
            float2 bv = *(const float2*)(vh + kk * 32 + j * 2);
            fma2(o2[0], a2, bc2(bv.x));
            fma2(o2[1], a2, bc2(bv.y));
        }
        float* ot = Xs + (h * 32 + j * 2) * XST + i2 * 2;
        *(u64*)ot         = o2[0];
        *(u64*)(ot + XST) = o2[1];
    }

    // ---- proj: out = O @ proj_w^T + b; one 192-col chunk x 12 K-tiles ----
    {
        float* dst = wb[0] + wk0 * BST + wc0;   // overlays Rs (dead)
        dst[0] = wr0.x; dst[BST] = wr0.y; dst[2 * BST] = wr0.z; dst[3 * BST] = wr0.w;
        if (two) {
            float* d2 = wb[0] + wk0 * BST + wc0 + 128;
            d2[0] = wr1.x; d2[BST] = wr1.y; d2[2 * BST] = wr1.z; d2[3 * BST] = wr1.w;
        }
    }
    __syncthreads();   // tile 0 staged; attention Ps/Rs reads + Xs writes done
    for (int t = 0; t < 12; t++) {
        if (t + 1 < 12) {
            const int nk = (t + 1) * KT;
            wr0 = *(const float4*)(proj_w + wc0 * 192 + nk + wk0);
            if (two) wr1 = *(const float4*)(proj_w + (wc0 + 128) * 192 + nk + wk0);
        }
        const float* bt = wb[t & 1];
        const float* xk = Xs + (t * KT) * XST;
        #pragma unroll 4
        for (int k = 0; k < KT; k++) {
            ulonglong2 aA = *(const ulonglong2*)(xk + k * XST + m0);
            const float* br = bt + k * BST + colT;
            float2 b01 = *(const float2*)br;
            float2 b23 = *(const float2*)(br + 2);
            float2 b45 = *(const float2*)(br + 4);
            u64 B0 = bc2(b01.x), B1 = bc2(b01.y), B2 = bc2(b23.x);
            u64 B3 = bc2(b23.y), B4 = bc2(b45.x), B5 = bc2(b45.y);
            fma2(acc[0][0], aA.x, B0); fma2(acc[1][0], aA.y, B0);
            fma2(acc[0][1], aA.x, B1); fma2(acc[1][1], aA.y, B1);
            fma2(acc[0][2], aA.x, B2); fma2(acc[1][2], aA.y, B2);
            fma2(acc[0][3], aA.x, B3); fma2(acc[1][3], aA.y, B3);
            fma2(acc[0][4], aA.x, B4); fma2(acc[1][4], aA.y, B4);
            fma2(acc[0][5], aA.x, B5); fma2(acc[1][5], aA.y, B5);
        }
        if (t + 1 < 12) {
            float* bn = wb[(t + 1) & 1];
            float* dst = bn + wk0 * BST + wc0;
            dst[0] = wr0.x; dst[BST] = wr0.y; dst[2 * BST] = wr0.z; dst[3 * BST] = wr0.w;
            if (two) {
                float* d2 = bn + wk0 * BST + wc0 + 128;
                d2[0] = wr1.x; d2[BST] = wr1.y; d2[2 * BST] = wr1.z; d2[3 * BST] = wr1.w;
            }
            __syncthreads();
        }
    }
    // proj epilogue: rows m0..m0+3, cols colT..colT+5
    {
        float2 pb01 = *(const float2*)(proj_b + colT);
        float2 pb23 = *(const float2*)(proj_b + colT + 2);
        float2 pb45 = *(const float2*)(proj_b + colT + 4);
        #pragma unroll
        for (int mp = 0; mp < 2; mp++) {
            float2 f[6];
            #pragma unroll
            for (int c = 0; c < 6; c++) f[c] = unpk(acc[mp][c]);
            const int m = m0 + 2 * mp;
            float* po = out + base + ((m >> 3) * 256 + (m & 7)) * 192 + colT;
            *(float2*)(po)     = make_float2(f[0].x + pb01.x, f[1].x + pb01.y);
            *(float2*)(po + 2) = make_float2(f[2].x + pb23.x, f[3].x + pb23.y);
            *(float2*)(po + 4) = make_float2(f[4].x + pb45.x, f[5].x + pb45.y);
            float* po2 = po + 192;   // row m+1 (same 8-block: m0 = rg*4)
            *(float2*)(po2)     = make_float2(f[0].y + pb01.x, f[1].y + pb01.y);
            *(float2*)(po2 + 2) = make_float2(f[2].y + pb23.x, f[3].y + pb23.y);
            *(float2*)(po2 + 4) = make_float2(f[4].y + pb45.x, f[5].y + pb45.y);
        }
    }
}

extern "C" void kernel_launch(void* const* d_in, const int* in_sizes, int n_in,
                              void* d_out, int out_size) {
    (void)in_sizes; (void)n_in; (void)out_size;
    cudaFuncSetAttribute(win_attn_kernel,
                         cudaFuncAttributeMaxDynamicSharedMemorySize, SMEM_BYTES);
    win_attn_kernel<<<4096, NT, SMEM_BYTES>>>(
        (const float*)d_in[0],   // x
        (const float*)d_in[1],   // qkv_w
        (const float*)d_in[2],   // proj_w
        (const float*)d_in[3],   // proj_b
        (const float*)d_in[4],   // rpb_table
        (float*)d_out);
}

// round 16
// speedup vs baseline: 1.1425x; 1.1425x over previous
#include <cuda_runtime.h>

// Fused Swin window attention, fp32 + packed f32x2 FMA. One CTA per 8x8 window.
// B=4, H=W=256, C=192, WS=8, NH=6, HD=32.
// R13 = R8 (8m x 6n weight-GEMM tiles, 256 threads, KT=16 double-buffered
// one-barrier pipeline, conflict-aware transpose, rpb overlay, Ps-aliased
// weight buffer) + explicit depth-1 software pipelining of all inner loops
// (load k+1 operands while computing k) to hide the 29-cycle LDS latency
// at 2 warps/SMSP.
//
// smem (floats):
//   Xs [192][68]  X^T (k-major, padded); reused as attn-out^T for proj
//   Qs [6][32][64], Ks [6][32][64]  d-major
//   Vs [6][64][32] token-major
//   Ps [64][68]   softmax probs (attention) / weight buf1 (GEMMs, 16x196)
//   Bt [16][196]  weight buf0 (GEMMs) / rpb table (attention)

#define XST 68
#define PST 68
#define BST 196
#define KT  16

#define SM_X 0
#define SM_Q 13056
#define SM_K 25344
#define SM_V 37632
#define SM_P 49920
#define SM_B 54272
#define SM_FLOATS 57472
#define SMEM_BYTES (SM_FLOATS * 4)

typedef unsigned long long u64;

__device__ __forceinline__ u64 bc2(float v) {
    u64 r;
    asm("mov.b64 %0, {%1, %1};" : "=l"(r) : "r"(__float_as_uint(v)));
    return r;
}
__device__ __forceinline__ void fma2(u64& d, u64 a, u64 b) {
    asm("fma.rn.f32x2 %0, %1, %2, %0;" : "+l"(d) : "l"(a), "l"(b));
}
__device__ __forceinline__ u64 mul2(u64 a, u64 b) {
    u64 r;
    asm("mul.rn.f32x2 %0, %1, %2;" : "=l"(r) : "l"(a), "l"(b));
    return r;
}
__device__ __forceinline__ float2 unpk(u64 a) {
    unsigned lo, hi;
    asm("mov.b64 {%0, %1}, %2;" : "=r"(lo), "=r"(hi) : "l"(a));
    return make_float2(__uint_as_float(lo), __uint_as_float(hi));
}

// 24-FMA2 block for the weight GEMMs (4 packed m-pairs x 6 n-cols)
#define GEMM_FMAS(AC, A0, A1, c01, c23, c45)                              \
    do {                                                                  \
        u64 B0 = bc2((c01).x), B1 = bc2((c01).y), B2 = bc2((c23).x);      \
        u64 B3 = bc2((c23).y), B4 = bc2((c45).x), B5 = bc2((c45).y);      \
        fma2(AC[0][0], (A0).x, B0); fma2(AC[1][0], (A0).y, B0);           \
        fma2(AC[2][0], (A1).x, B0); fma2(AC[3][0], (A1).y, B0);           \
        fma2(AC[0][1], (A0).x, B1); fma2(AC[1][1], (A0).y, B1);           \
        fma2(AC[2][1], (A1).x, B1); fma2(AC[3][1], (A1).y, B1);           \
        fma2(AC[0][2], (A0).x, B2); fma2(AC[1][2], (A0).y, B2);           \
        fma2(AC[2][2], (A1).x, B2); fma2(AC[3][2], (A1).y, B2);           \
        fma2(AC[0][3], (A0).x, B3); fma2(AC[1][3], (A0).y, B3);           \
        fma2(AC[2][3], (A1).x, B3); fma2(AC[3][3], (A1).y, B3);           \
        fma2(AC[0][4], (A0).x, B4); fma2(AC[1][4], (A0).y, B4);           \
        fma2(AC[2][4], (A1).x, B4); fma2(AC[3][4], (A1).y, B4);           \
        fma2(AC[0][5], (A0).x, B5); fma2(AC[1][5], (A0).y, B5);           \
        fma2(AC[2][5], (A1).x, B5); fma2(AC[3][5], (A1).y, B5);           \
    } while (0)

__global__ __launch_bounds__(256, 1)
void win_attn_kernel(const float* __restrict__ x,
                     const float* __restrict__ qkv_w,
                     const float* __restrict__ proj_w,
                     const float* __restrict__ proj_b,
                     const float* __restrict__ rpb,
                     float* __restrict__ out)
{
    extern __shared__ float sm[];
    float* Xs = sm + SM_X;
    float* Qs = sm + SM_Q;
    float* Ks = sm + SM_K;
    float* Vs = sm + SM_V;
    float* Ps = sm + SM_P;
    float* Rs = sm + SM_B;       // rpb table, attention phase only
    float* wb[2];
    wb[0] = sm + SM_B;           // weight buf0 (GEMM phases)
    wb[1] = sm + SM_P;           // weight buf1 aliases Ps

    const int tid  = threadIdx.x;
    const int lane = tid & 31;
    const int w    = tid >> 5;
    // weight-GEMM thread tile: rows mg*8..mg*8+7, cols colT..colT+5
    const int mg   = lane >> 2;
    const int ls   = lane & 3;
    const int colT = w * 24 + ls * 6;
    // attention mapping (4m x 4n)
    const int i = tid >> 4;
    const int j = tid & 15;

    const int blk = blockIdx.x;
    const int b  = blk >> 10;
    const int wy = (blk >> 5) & 31;
    const int wx = blk & 31;
    const int base = ((b * 256 + wy * 8) * 256 + wx * 8) * 192;

    // ---- load X window transposed into Xs[k][m] (conflict-aware mapping) ----
    {
        const int dm = (tid >> 2) & 7;
        const int dc = tid & 3;
        const int wv = tid >> 5;
        const int m  = wv * 8 + dm;
        const float* src = x + base + (wv * 256 + dm) * 192 + dc * 4;
        float* dstb = Xs + dc * 4 * XST + m;
        #pragma unroll
        for (int p = 0; p < 12; p++) {
            float4 v = *(const float4*)(src + p * 16);
            float* dst = dstb + p * 16 * XST;
            dst[0]       = v.x;
            dst[XST]     = v.y;
            dst[2 * XST] = v.z;
            dst[3 * XST] = v.w;
        }
    }

    const u64 sc2 = bc2(0.17677669529663687f);  // 32^-0.5 packed

    // staging coords: tile = 16k x 192n = 768 float4; 3 per thread.
    int wc[3], wk[3];
    #pragma unroll
    for (int p = 0; p < 3; p++) {
        int idx = p * 256 + tid;
        wc[p] = idx >> 2;
        wk[p] = (idx & 3) * 4;
    }

    float4 wr[3];
    // prologue: QKV chunk 0 (Q), tile 0
    #pragma unroll
    for (int p = 0; p < 3; p++)
        wr[p] = *(const float4*)(qkv_w + wc[p] * 192 + wk[p]);
    #pragma unroll
    for (int p = 0; p < 3; p++) {
        float* dst = wb[0] + wk[p] * BST + wc[p];
        dst[0]       = wr[p].x;
        dst[BST]     = wr[p].y;
        dst[2 * BST] = wr[p].z;
        dst[3 * BST] = wr[p].w;
    }
    __syncthreads();   // tile 0 staged; also orders Xs stores

    // ---- GEMM1: QKV = X @ qkv_w^T; 3 chunks (Q,K,V) x 12 K-tiles ----
    u64 acc[4][6] = {};
    for (int t = 0; t < 36; t++) {
        const int q = t % 12;
        if (t + 1 < 36) {
            const int nn = ((t + 1) / 12) * 192;
            const int nk = ((t + 1) % 12) * KT;
            #pragma unroll
            for (int p = 0; p < 3; p++)
                wr[p] = *(const float4*)(qkv_w + (nn + wc[p]) * 192 + nk + wk[p]);
        }
        const float* bt = wb[t & 1];
        const float* xk = Xs + (q * KT) * XST + mg * 8;
        const float* bb = bt + colT;
        // depth-1 pipelined K loop: load k+1 while computing k
        ulonglong2 cA0 = *(const ulonglong2*)(xk);
        ulonglong2 cA1 = *(const ulonglong2*)(xk + 4);
        float2 c01 = *(const float2*)(bb);
        float2 c23 = *(const float2*)(bb + 2);
        float2 c45 = *(const float2*)(bb + 4);
        #pragma unroll
        for (int k = 0; k < KT - 1; k++) {
            const float* xn = xk + (k + 1) * XST;
            const float* bn2 = bb + (k + 1) * BST;
            ulonglong2 nA0 = *(const ulonglong2*)(xn);
            ulonglong2 nA1 = *(const ulonglong2*)(xn + 4);
            float2 n01 = *(const float2*)(bn2);
            float2 n23 = *(const float2*)(bn2 + 2);
            float2 n45 = *(const float2*)(bn2 + 4);
            GEMM_FMAS(acc, cA0, cA1, c01, c23, c45);
            cA0 = nA0; cA1 = nA1; c01 = n01; c23 = n23; c45 = n45;
        }
        GEMM_FMAS(acc, cA0, cA1, c01, c23, c45);
        if (t + 1 < 36) {
            float* bn = wb[(t + 1) & 1];
            #pragma unroll
            for (int p = 0; p < 3; p++) {
                float* dst = bn + wk[p] * BST + wc[p];
                dst[0]       = wr[p].x;
                dst[BST]     = wr[p].y;
                dst[2 * BST] = wr[p].z;
                dst[3 * BST] = wr[p].w;
            }
        }
        if (q == 11) {
            const int ch = t / 12;       // 0=Q 1=K 2=V
            if (ch == 0) {
                #pragma unroll
                for (int c = 0; c < 6; c++) {
                    const int col = colT + c;
                    float* qp = Qs + (col >> 5) * 2048 + (col & 31) * 64 + mg * 8;
                    ulonglong2 lo, hi;
                    lo.x = mul2(acc[0][c], sc2); lo.y = mul2(acc[1][c], sc2);
                    hi.x = mul2(acc[2][c], sc2); hi.y = mul2(acc[3][c], sc2);
                    *(ulonglong2*)qp       = lo;
                    *(ulonglong2*)(qp + 4) = hi;
                }
            } else if (ch == 1) {
                #pragma unroll
                for (int c = 0; c < 6; c++) {
                    const int col = colT + c;
                    float* kp = Ks + (col >> 5) * 2048 + (col & 31) * 64 + mg * 8;
                    ulonglong2 lo, hi;
                    lo.x = acc[0][c]; lo.y = acc[1][c];
                    hi.x = acc[2][c]; hi.y = acc[3][c];
                    *(ulonglong2*)kp       = lo;
                    *(ulonglong2*)(kp + 4) = hi;
                }
            } else {
                #pragma unroll
                for (int c = 0; c < 6; c++) {
                    const int col = colT + c;
                    float* vp = Vs + (col >> 5) * 2048 + (col & 31);
                    #pragma unroll
                    for (int mp = 0; mp < 4; mp++) {
                        float2 f = unpk(acc[mp][c]);
                        vp[(mg * 8 + 2 * mp) * 32]     = f.x;
                        vp[(mg * 8 + 2 * mp + 1) * 32] = f.y;
                    }
                }
            }
            #pragma unroll
            for (int mp = 0; mp < 4; mp++)
                #pragma unroll
                for (int c = 0; c < 6; c++) acc[mp][c] = 0ull;
        }
        __syncthreads();
    }

    // ---- stage rpb into Rs (overlays wb0; all wb0 reads done) + proj prefetch ----
    for (int t = tid; t < 1350; t += 256) Rs[t] = rpb[t];
    #pragma unroll
    for (int p = 0; p < 3; p++)
        wr[p] = *(const float4*)(proj_w + wc[p] * 192 + wk[p]);
    __syncthreads();   // Rs ready

    // ---- rpb offsets for this thread's S tile ----
    int ridx[4][4];
    #pragma unroll
    for (int di = 0; di < 4; di++) {
        int m = i * 4 + di, qr = m >> 3, qc = m & 7;
        #pragma unroll
        for (int dj = 0; dj < 4; dj++) {
            int n = j * 4 + dj, kr = n >> 3, kc = n & 7;
            ridx[di][dj] = ((qr - kr + 7) * 15 + (qc - kc + 7)) * 6;
        }
    }

    // ---- attention per head ----
    for (int h = 0; h < 6; h++) {
        const float* qh = Qs + h * 2048 + i * 4;
        const float* kh = Ks + h * 2048 + j * 4;
        u64 s2[4][2] = {};
        {
            // pipelined S-GEMM over d
            float4 cQ      = *(const float4*)(qh);
            ulonglong2 cK  = *(const ulonglong2*)(kh);
            #pragma unroll 4
            for (int d = 0; d < 31; d++) {
                float4 nQ     = *(const float4*)(qh + (d + 1) * 64);
                ulonglong2 nK = *(const ulonglong2*)(kh + (d + 1) * 64);
                u64 a0 = bc2(cQ.x), a1 = bc2(cQ.y), a2b = bc2(cQ.z), a3 = bc2(cQ.w);
                fma2(s2[0][0], a0, cK.x);  fma2(s2[0][1], a0, cK.y);
                fma2(s2[1][0], a1, cK.x);  fma2(s2[1][1], a1, cK.y);
                fma2(s2[2][0], a2b, cK.x); fma2(s2[2][1], a2b, cK.y);
                fma2(s2[3][0], a3, cK.x);  fma2(s2[3][1], a3, cK.y);
                cQ = nQ; cK = nK;
            }
            u64 a0 = bc2(cQ.x), a1 = bc2(cQ.y), a2b = bc2(cQ.z), a3 = bc2(cQ.w);
            fma2(s2[0][0], a0, cK.x);  fma2(s2[0][1], a0, cK.y);
            fma2(s2[1][0], a1, cK.x);  fma2(s2[1][1], a1, cK.y);
            fma2(s2[2][0], a2b, cK.x); fma2(s2[2][1], a2b, cK.y);
            fma2(s2[3][0], a3, cK.x);  fma2(s2[3][1], a3, cK.y);
        }
        float p[4][4];
        #pragma unroll
        for (int di = 0; di < 4; di++) {
            float2 s01 = unpk(s2[di][0]), s23 = unpk(s2[di][1]);
            float sv0 = s01.x + Rs[ridx[di][0] + h];
            float sv1 = s01.y + Rs[ridx[di][1] + h];
            float sv2 = s23.x + Rs[ridx[di][2] + h];
            float sv3 = s23.y + Rs[ridx[di][3] + h];
            float mx = fmaxf(fmaxf(sv0, sv1), fmaxf(sv2, sv3));
            mx = fmaxf(mx, __shfl_xor_sync(0xffffffffu, mx, 8));
            mx = fmaxf(mx, __shfl_xor_sync(0xffffffffu, mx, 4));
            mx = fmaxf(mx, __shfl_xor_sync(0xffffffffu, mx, 2));
            mx = fmaxf(mx, __shfl_xor_sync(0xffffffffu, mx, 1));
            float e0 = __expf(sv0 - mx), e1 = __expf(sv1 - mx);
            float e2 = __expf(sv2 - mx), e3 = __expf(sv3 - mx);
            float sum = (e0 + e1) + (e2 + e3);
            sum += __shfl_xor_sync(0xffffffffu, sum, 8);
            sum += __shfl_xor_sync(0xffffffffu, sum, 4);
            sum += __shfl_xor_sync(0xffffffffu, sum, 2);
            sum += __shfl_xor_sync(0xffffffffu, sum, 1);
            float inv = __frcp_rn(sum);
            p[di][0] = e0 * inv; p[di][1] = e1 * inv;
            p[di][2] = e2 * inv; p[di][3] = e3 * inv;
        }
        __syncthreads();   // prior Ps readers done
        #pragma unroll
        for (int dj = 0; dj < 4; dj++)
            *(float4*)(Ps + (j * 4 + dj) * PST + i * 4) =
                make_float4(p[0][dj], p[1][dj], p[2][dj], p[3][dj]);
        __syncthreads();   // Ps ready

        // pipelined PV over kk
        const float* ph = Ps + i * 4;
        const float* vh = Vs + h * 2048 + j * 2;
        u64 o2[2][2] = {};
        {
            ulonglong2 cP = *(const ulonglong2*)(ph);
            float2 cV     = *(const float2*)(vh);
            #pragma unroll 4
            for (int kk = 0; kk < 63; kk++) {
                ulonglong2 nP = *(const ulonglong2*)(ph + (kk + 1) * PST);
                float2 nV     = *(const float2*)(vh + (kk + 1) * 32);
                u64 b0 = bc2(cV.x), b1 = bc2(cV.y);
                fma2(o2[0][0], cP.x, b0); fma2(o2[0][1], cP.x, b1);
                fma2(o2[1][0], cP.y, b0); fma2(o2[1][1], cP.y, b1);
                cP = nP; cV = nV;
            }
            u64 b0 = bc2(cV.x), b1 = bc2(cV.y);
            fma2(o2[0][0], cP.x, b0); fma2(o2[0][1], cP.x, b1);
            fma2(o2[1][0], cP.y, b0); fma2(o2[1][1], cP.y, b1);
        }
        float* ot = Xs + (h * 32 + j * 2) * XST + i * 4;
        ulonglong2 c0, c1;
        c0.x = o2[0][0]; c0.y = o2[1][0];
        c1.x = o2[0][1]; c1.y = o2[1][1];
        *(ulonglong2*)ot         = c0;
        *(ulonglong2*)(ot + XST) = c1;
    }

    // ---- proj: out = O @ proj_w^T + b; one 192-col chunk x 12 K-tiles ----
    #pragma unroll
    for (int p = 0; p < 3; p++) {
        float* dst = wb[0] + wk[p] * BST + wc[p];   // overlays Rs (dead)
        dst[0]       = wr[p].x;
        dst[BST]     = wr[p].y;
        dst[2 * BST] = wr[p].z;
        dst[3 * BST] = wr[p].w;
    }
    __syncthreads();   // tile 0 staged; attention Ps/Rs reads + Xs writes done
    for (int t = 0; t < 12; t++) {
        if (t + 1 < 12) {
            const int nk = (t + 1) * KT;
            #pragma unroll
            for (int p = 0; p < 3; p++)
                wr[p] = *(const float4*)(proj_w + wc[p] * 192 + nk + wk[p]);
        }
        const float* bt = wb[t & 1];
        const float* xk = Xs + (t * KT) * XST + mg * 8;
        const float* bb = bt + colT;
        ulonglong2 cA0 = *(const ulonglong2*)(xk);
        ulonglong2 cA1 = *(const ulonglong2*)(xk + 4);
        float2 c01 = *(const float2*)(bb);
        float2 c23 = *(const float2*)(bb + 2);
        float2 c45 = *(const float2*)(bb + 4);
        #pragma unroll
        for (int k = 0; k < KT - 1; k++) {
            const float* xn = xk + (k + 1) * XST;
            const float* bn2 = bb + (k + 1) * BST;
            ulonglong2 nA0 = *(const ulonglong2*)(xn);
            ulonglong2 nA1 = *(const ulonglong2*)(xn + 4);
            float2 n01 = *(const float2*)(bn2);
            float2 n23 = *(const float2*)(bn2 + 2);
            float2 n45 = *(const float2*)(bn2 + 4);
            GEMM_FMAS(acc, cA0, cA1, c01, c23, c45);
            cA0 = nA0; cA1 = nA1; c01 = n01; c23 = n23; c45 = n45;
        }
        GEMM_FMAS(acc, cA0, cA1, c01, c23, c45);
        if (t + 1 < 12) {
            float* bn = wb[(t + 1) & 1];
            #pragma unroll
            for (int p = 0; p < 3; p++) {
                float* dst = bn + wk[p] * BST + wc[p];
                dst[0]       = wr[p].x;
                dst[BST]     = wr[p].y;
                dst[2 * BST] = wr[p].z;
                dst[3 * BST] = wr[p].w;
            }
            __syncthreads();
        }
    }
    // proj epilogue: rows mg*8..+7, cols colT..colT+5
    {
        float2 pb01 = *(const float2*)(proj_b + colT);
        float2 pb23 = *(const float2*)(proj_b + colT + 2);
        float2 pb45 = *(const float2*)(proj_b + colT + 4);
        #pragma unroll
        for (int mp = 0; mp < 4; mp++) {
            float2 f[6];
            #pragma unroll
            for (int c = 0; c < 6; c++) f[c] = unpk(acc[mp][c]);
            const int m = mg * 8 + 2 * mp;
            float* po = out + base + ((m >> 3) * 256 + (m & 7)) * 192 + colT;
            *(float2*)(po)     = make_float2(f[0].x + pb01.x, f[1].x + pb01.y);
            *(float2*)(po + 2) = make_float2(f[2].x + pb23.x, f[3].x + pb23.y);
            *(float2*)(po + 4) = make_float2(f[4].x + pb45.x, f[5].x + pb45.y);
            float* po2 = po + 192;   // row m+1 (same 8-block)
            *(float2*)(po2)     = make_float2(f[0].y + pb01.x, f[1].y + pb01.y);
            *(float2*)(po2 + 2) = make_float2(f[2].y + pb23.x, f[3].y + pb23.y);
            *(float2*)(po2 + 4) = make_float2(f[4].y + pb45.x, f[5].y + pb45.y);
        }
    }
}

extern "C" void kernel_launch(void* const* d_in, const int* in_sizes, int n_in,
                              void* d_out, int out_size) {
    (void)in_sizes; (void)n_in; (void)out_size;
    cudaFuncSetAttribute(win_attn_kernel,
                         cudaFuncAttributeMaxDynamicSharedMemorySize, SMEM_BYTES);
    win_attn_kernel<<<4096, 256, SMEM_BYTES>>>(
        (const float*)d_in[0],   // x
        (const float*)d_in[1],   // qkv_w
        (const float*)d_in[2],   // proj_w
        (const float*)d_in[3],   // proj_b
        (const float*)d_in[4],   // rpb_table
        (float*)d_out);
}